// round 8
// baseline (speedup 1.0000x reference)
#include <cuda_runtime.h>
#include <cstdint>
#include <math.h>

#define B_TOTAL 16384
#define F_FIELDS 39
#define E_DIM 64
#define U_DIM 128
#define BTILE 64
#define THREADS 256
#define NPAIR 2080
#define KPAD  2112
#define NCHUNK 33
#define FSTR 65
#define ASTR 72
#define BSTR 72
// smem (floats): sF 64*65=4160 | sA 64*72=4608 | sB 128*72=9216 | sP 2112
#define OFF_A 4160
#define OFF_B 8768
#define OFF_P 17984
#define SMEM_FLOATS 20096
#define SMEM_BYTES  (SMEM_FLOATS * 4)   // 80384 B -> 2 CTAs/SM

__device__ float    g_fsum[B_TOTAL * E_DIM];
__device__ unsigned g_T[U_DIM * KPAD];     // rna-tf32 bits of packed symmetric W (perm layout)
__device__ unsigned g_pair[KPAD];          // (i<<8)|j per PERMUTED packed k index

__device__ __forceinline__ unsigned f2tf(float x) {
    unsigned y; asm("cvt.rna.tf32.f32 %0, %1;" : "=r"(y) : "f"(x)); return y;
}
__device__ __forceinline__ uint32_t smem_u32(const void* p) {
    uint32_t a;
    asm("{ .reg .u64 t; cvta.to.shared.u64 t, %1; cvt.u32.u64 %0, t; }" : "=r"(a) : "l"(p));
    return a;
}
__device__ __forceinline__ void cp16(uint32_t dst, const void* src) {
    asm volatile("cp.async.cg.shared.global [%0], [%1], 16;" :: "r"(dst), "l"(src) : "memory");
}
__device__ __forceinline__ void cp_commit() {
    asm volatile("cp.async.commit_group;" ::: "memory");
}
__device__ __forceinline__ void cp_wait0() {
    asm volatile("cp.async.wait_group 0;" ::: "memory");
}
__device__ __forceinline__ void mma8(float* c, unsigned a0, unsigned a1,
                                     unsigned a2, unsigned a3,
                                     unsigned b0, unsigned b1) {
    asm volatile(
        "mma.sync.aligned.m16n8k8.row.col.f32.tf32.tf32.f32 "
        "{%0,%1,%2,%3}, {%4,%5,%6,%7}, {%8,%9}, {%0,%1,%2,%3};"
        : "+f"(c[0]), "+f"(c[1]), "+f"(c[2]), "+f"(c[3])
        : "r"(a0), "r"(a1), "r"(a2), "r"(a3), "r"(b0), "r"(b1));
}

// ---------------- pair table: packed upper-tri (i<=j), k-permuted in 8-groups ----------------
__global__ void pairs_kernel() {
    int t = blockIdx.x * blockDim.x + threadIdx.x;
    if (t >= KPAD) return;
    int g = t >> 3, n = t & 7;
    int src = g * 8 + (n >> 1) + ((n & 1) << 2);
    unsigned val = 0;
    if (src < NPAIR) {
        double d = 129.0 * 129.0 - 8.0 * (double)src;
        int i = (int)((129.0 - sqrt(d)) * 0.5);
        if (i < 0) i = 0; if (i > 63) i = 63;
        while (i > 0  && i * (129 - i) / 2 > src) --i;
        while (i < 63 && (i + 1) * (128 - i) / 2 <= src) ++i;
        int j = i + (src - i * (129 - i) / 2);
        val = ((unsigned)i << 8) | (unsigned)j;
    }
    g_pair[t] = val;
}

// ---------------- feat_sum over F ----------------
__global__ void fsum_kernel(const float* __restrict__ embeds) {
    int idx = blockIdx.x * blockDim.x + threadIdx.x;
    int b = idx >> 4;
    int e4 = idx & 15;
    const float4* p = reinterpret_cast<const float4*>(embeds)
                      + (size_t)b * (F_FIELDS * E_DIM / 4) + e4;
    float4 s = make_float4(0.f, 0.f, 0.f, 0.f);
#pragma unroll
    for (int f = 0; f < F_FIELDS; ++f) {
        float4 v = p[f * (E_DIM / 4)];
        s.x += v.x; s.y += v.y; s.z += v.z; s.w += v.w;
    }
    reinterpret_cast<float4*>(g_fsum)[idx] = s;
}

// ---------------- packed symmetric T[u,k] = rna_tf32(W_ij + W_ji), perm layout ----------------
__global__ void tconv_kernel(const float* __restrict__ W) {
    int idx = blockIdx.x * blockDim.x + threadIdx.x;   // u*KPAD + k
    int u = idx / KPAD;
    int k = idx - u * KPAD;
    unsigned p = g_pair[k];
    float v = 0.f;
    if (p != 0 || k == 0) {
        int i = p >> 8, j = p & 255;
        v = W[u * 4096 + i * 64 + j];
        if (i != j) v += W[u * 4096 + j * 64 + i];
    }
    g_T[idx] = f2tf(v);
}

// ---------------- main GEMM: C[64b x 128u] += A[64 x 64k] * B[64k x 128] ----------------
// 256 threads = 8 warps: 4 tile-warps (2m x 2n of 32x64 tiles) x 2 k-split.
// Single-buffered sA/sB (78.5 KB total) -> 2 independent CTAs per SM provide
// the phase overlap that intra-CTA double buffering failed to deliver.
__global__ void __launch_bounds__(THREADS, 2)
quad_kernel(float* __restrict__ out) {
    extern __shared__ float sm[];
    float*    sF = sm;
    float*    sA = sm + OFF_A;
    float*    sB = sm + OFF_B;
    unsigned* sP = (unsigned*)(sm + OFF_P);

    const int tid  = threadIdx.x;
    const int lane = tid & 31;
    const int warp = tid >> 5;
    const int twarp = warp & 3;                // tile-warp id
    const int kw    = warp >> 2;               // k-split id (0/1)
    const int l4 = lane >> 2, k4 = lane & 3;
    const int row_base = (twarp & 1) * 32;     // 2-way m split
    const int col_base = (twarp >> 1) * 64;    // 2-way n split
    const int b0 = blockIdx.x * BTILE;

    // gen/stage roles
    const int rA = tid & 63;                   // A row (b)
    const int khA = (tid >> 6) * 16;           // 16-col slice
    const int rB = tid >> 1;                   // B row (u), 0..127
    const int khB = (tid & 1) * 32;            // 32-col slice

    const uint32_t sB_u = smem_u32(sB);

    // ---- stage f tile (stride 65 -> conflict-free scattered gen reads) ----
    {
        const float4* src = reinterpret_cast<const float4*>(
            g_fsum + (size_t)(b0 + rA) * E_DIM + khA);
#pragma unroll
        for (int t = 0; t < 4; ++t) {
            float4 v = src[t];
            sF[rA * FSTR + khA + 4*t + 0] = v.x;
            sF[rA * FSTR + khA + 4*t + 1] = v.y;
            sF[rA * FSTR + khA + 4*t + 2] = v.z;
            sF[rA * FSTR + khA + 4*t + 3] = v.w;
        }
    }
    for (int k = tid; k < KPAD; k += THREADS) sP[k] = g_pair[k];
    __syncthreads();

    float acc[2][8][4];
#pragma unroll
    for (int mt = 0; mt < 2; ++mt)
#pragma unroll
        for (int nt = 0; nt < 8; ++nt)
#pragma unroll
            for (int x = 0; x < 4; ++x) acc[mt][nt][x] = 0.f;

#pragma unroll 1
    for (int c = 0; c < NCHUNK; ++c) {
        // ---- stage B(c) via cp.async (prev MMA finished at loop-end barrier) ----
        {
            const unsigned* src = g_T + (size_t)rB * KPAD + c * 64 + khB;
            uint32_t dst = sB_u + (uint32_t)(rB * BSTR + khB) * 4u;
#pragma unroll
            for (int q = 0; q < 8; ++q) cp16(dst + 16u * q, src + 4 * q);
            cp_commit();
        }
        // ---- gen A(c) (overlaps cp.async flight) ----
        {
            const int kb = c * 64 + khA;
            const int fb = rA * FSTR;
            float* dst = sA + rA * ASTR + khA;
#pragma unroll
            for (int q = 0; q < 4; ++q) {
                unsigned p0 = sP[kb + 4*q + 0], p1 = sP[kb + 4*q + 1];
                unsigned p2 = sP[kb + 4*q + 2], p3 = sP[kb + 4*q + 3];
                float4 v;
                v.x = __uint_as_float(f2tf(sF[fb + (p0 >> 8)] * sF[fb + (p0 & 255)]));
                v.y = __uint_as_float(f2tf(sF[fb + (p1 >> 8)] * sF[fb + (p1 & 255)]));
                v.z = __uint_as_float(f2tf(sF[fb + (p2 >> 8)] * sF[fb + (p2 & 255)]));
                v.w = __uint_as_float(f2tf(sF[fb + (p3 >> 8)] * sF[fb + (p3 & 255)]));
                *reinterpret_cast<float4*>(dst + 4*q) = v;
            }
        }
        cp_wait0();
        __syncthreads();

        // ---- MMA over this warp's k-half of chunk c ----
#pragma unroll
        for (int kx = 0; kx < 4; ++kx) {
            const int kcol = (kw * 4 + kx) * 8 + k4 * 2;
            float2 a0[2], a1[2];
#pragma unroll
            for (int mt = 0; mt < 2; ++mt) {
                const float* ap = sA + (row_base + mt * 16 + l4) * ASTR + kcol;
                a0[mt] = *reinterpret_cast<const float2*>(ap);
                a1[mt] = *reinterpret_cast<const float2*>(ap + 8 * ASTR);
            }
#pragma unroll
            for (int nt = 0; nt < 8; ++nt) {
                float2 bb = *reinterpret_cast<const float2*>(
                    sB + (col_base + nt * 8 + l4) * BSTR + kcol);
                unsigned bf0 = __float_as_uint(bb.x);
                unsigned bf1 = __float_as_uint(bb.y);
#pragma unroll
                for (int mt = 0; mt < 2; ++mt)
                    mma8(acc[mt][nt],
                         __float_as_uint(a0[mt].x), __float_as_uint(a1[mt].x),
                         __float_as_uint(a0[mt].y), __float_as_uint(a1[mt].y),
                         bf0, bf1);
            }
        }
        __syncthreads();
    }

    // ---- epilogue: sum k-split partials via smem (reuse sA/sB region), STG ----
    float4* sRed = reinterpret_cast<float4*>(sm + OFF_A);   // 16*128 float4 = 32 KB
    if (kw == 1) {
        const int idx = tid - 128;
#pragma unroll
        for (int mt = 0; mt < 2; ++mt)
#pragma unroll
            for (int nt = 0; nt < 8; ++nt) {
                int q = mt * 8 + nt;
                sRed[q * 128 + idx] = make_float4(acc[mt][nt][0], acc[mt][nt][1],
                                                  acc[mt][nt][2], acc[mt][nt][3]);
            }
    }
    __syncthreads();
    if (kw == 0) {
#pragma unroll
        for (int mt = 0; mt < 2; ++mt) {
#pragma unroll
            for (int nt = 0; nt < 8; ++nt) {
                int q = mt * 8 + nt;
                float4 p = sRed[q * 128 + tid];
                float2 v0 = make_float2(acc[mt][nt][0] + p.x, acc[mt][nt][1] + p.y);
                float2 v1 = make_float2(acc[mt][nt][2] + p.z, acc[mt][nt][3] + p.w);
                const int rr = b0 + row_base + mt * 16 + l4;
                const int cc = col_base + nt * 8 + k4 * 2;
                *reinterpret_cast<float2*>(out + (size_t)rr * U_DIM + cc) = v0;
                *reinterpret_cast<float2*>(out + (size_t)(rr + 8) * U_DIM + cc) = v1;
            }
        }
    }
}

extern "C" void kernel_launch(void* const* d_in, const int* in_sizes, int n_in,
                              void* d_out, int out_size) {
    const float* embeds = (const float*)d_in[0];   // (16384, 39, 64)
    const float* W      = (const float*)d_in[1];   // (128, 64, 64)
    float* out          = (float*)d_out;           // (16384, 128)

    static int smem_set = 0;
    if (!smem_set) {
        cudaFuncSetAttribute(quad_kernel,
                             cudaFuncAttributeMaxDynamicSharedMemorySize, SMEM_BYTES);
        smem_set = 1;
    }

    pairs_kernel<<<(KPAD + 255) / 256, 256>>>();
    fsum_kernel<<<(B_TOTAL * (E_DIM / 4)) / 256, 256>>>(embeds);
    tconv_kernel<<<(U_DIM * KPAD) / 256, 256>>>(W);
    quad_kernel<<<B_TOTAL / BTILE, THREADS, SMEM_BYTES>>>(out);
}

// round 9
// speedup vs baseline: 1.4602x; 1.4602x over previous
#include <cuda_runtime.h>
#include <cstdint>
#include <math.h>

#define B_TOTAL 16384
#define F_FIELDS 39
#define E_DIM 64
#define U_DIM 128
#define BTILE 128
#define THREADS 384          // 8 consumer warps + 4 producer warps
#define NPAIR 2080
#define KPAD  2112
#define NCHUNK 33
#define FSTR 65
#define ASTR 72
#define BSTR 72
#define STAGE 9216           // 128*72 floats per stage
// smem float offsets
#define OFF_A0 8320
#define OFF_A1 17536
#define OFF_B0 26752
#define OFF_B1 35968
#define OFF_P  45184
#define SMEM_FLOATS 47296
#define SMEM_BYTES  (SMEM_FLOATS * 4)   // 189184 B, 1 CTA/SM

// named barrier ids (0 reserved for __syncthreads)
#define FULL0 1
#define FULL1 2
#define EMPTY0 3
#define EMPTY1 4

__device__ float    g_fsum[B_TOTAL * E_DIM];
__device__ unsigned g_T[U_DIM * KPAD];     // rna-tf32 bits of packed symmetric W (perm layout)
__device__ unsigned g_pair[KPAD];          // (i<<8)|j per PERMUTED packed k index

__device__ __forceinline__ unsigned f2tf(float x) {
    unsigned y; asm("cvt.rna.tf32.f32 %0, %1;" : "=r"(y) : "f"(x)); return y;
}
__device__ __forceinline__ uint32_t smem_u32(const void* p) {
    uint32_t a;
    asm("{ .reg .u64 t; cvta.to.shared.u64 t, %1; cvt.u32.u64 %0, t; }" : "=r"(a) : "l"(p));
    return a;
}
__device__ __forceinline__ void cp16(uint32_t dst, const void* src) {
    asm volatile("cp.async.cg.shared.global [%0], [%1], 16;" :: "r"(dst), "l"(src) : "memory");
}
__device__ __forceinline__ void cp_commit() {
    asm volatile("cp.async.commit_group;" ::: "memory");
}
__device__ __forceinline__ void cp_wait0() {
    asm volatile("cp.async.wait_group 0;" ::: "memory");
}
__device__ __forceinline__ void bar_sync(int id) {
    asm volatile("bar.sync %0, %1;" :: "r"(id), "n"(THREADS) : "memory");
}
__device__ __forceinline__ void bar_arrive(int id) {
    asm volatile("bar.arrive %0, %1;" :: "r"(id), "n"(THREADS) : "memory");
}
__device__ __forceinline__ void mma8(float* c, unsigned a0, unsigned a1,
                                     unsigned a2, unsigned a3,
                                     unsigned b0, unsigned b1) {
    asm volatile(
        "mma.sync.aligned.m16n8k8.row.col.f32.tf32.tf32.f32 "
        "{%0,%1,%2,%3}, {%4,%5,%6,%7}, {%8,%9}, {%0,%1,%2,%3};"
        : "+f"(c[0]), "+f"(c[1]), "+f"(c[2]), "+f"(c[3])
        : "r"(a0), "r"(a1), "r"(a2), "r"(a3), "r"(b0), "r"(b1));
}

// ---------------- pair table: packed upper-tri (i<=j), k-permuted in 8-groups ----------------
__global__ void pairs_kernel() {
    int t = blockIdx.x * blockDim.x + threadIdx.x;
    if (t >= KPAD) return;
    int g = t >> 3, n = t & 7;
    int src = g * 8 + (n >> 1) + ((n & 1) << 2);
    unsigned val = 0;
    if (src < NPAIR) {
        double d = 129.0 * 129.0 - 8.0 * (double)src;
        int i = (int)((129.0 - sqrt(d)) * 0.5);
        if (i < 0) i = 0; if (i > 63) i = 63;
        while (i > 0  && i * (129 - i) / 2 > src) --i;
        while (i < 63 && (i + 1) * (128 - i) / 2 <= src) ++i;
        int j = i + (src - i * (129 - i) / 2);
        val = ((unsigned)i << 8) | (unsigned)j;
    }
    g_pair[t] = val;
}

// ---------------- feat_sum over F ----------------
__global__ void fsum_kernel(const float* __restrict__ embeds) {
    int idx = blockIdx.x * blockDim.x + threadIdx.x;
    int b = idx >> 4;
    int e4 = idx & 15;
    const float4* p = reinterpret_cast<const float4*>(embeds)
                      + (size_t)b * (F_FIELDS * E_DIM / 4) + e4;
    float4 s = make_float4(0.f, 0.f, 0.f, 0.f);
#pragma unroll
    for (int f = 0; f < F_FIELDS; ++f) {
        float4 v = p[f * (E_DIM / 4)];
        s.x += v.x; s.y += v.y; s.z += v.z; s.w += v.w;
    }
    reinterpret_cast<float4*>(g_fsum)[idx] = s;
}

// ---------------- packed symmetric T[u,k] = rna_tf32(W_ij + W_ji), perm layout ----------------
__global__ void tconv_kernel(const float* __restrict__ W) {
    int idx = blockIdx.x * blockDim.x + threadIdx.x;   // u*KPAD + k
    int u = idx / KPAD;
    int k = idx - u * KPAD;
    unsigned p = g_pair[k];
    float v = 0.f;
    if (p != 0 || k == 0) {
        int i = p >> 8, j = p & 255;
        v = W[u * 4096 + i * 64 + j];
        if (i != j) v += W[u * 4096 + j * 64 + i];
    }
    g_T[idx] = f2tf(v);
}

// ---------------- main GEMM: warp-specialized producer/consumer ----------------
// C[128b x 128u] += A[128 x 64k] * B[64k x 128], 33 chunks over packed K=2112.
// Warps 0-7: consumers (4m x 2n grid, 32x64 tiles) - only frag LDS + HMMA.
// Warps 8-11: producers - gen A(c) from sF + cp.async B(c), 2-stage ring.
// Handoff via named barriers: FULL(s)=producers arrive/consumers sync,
// EMPTY(s)=consumers arrive/producers sync. Count 384 each.
__global__ void __launch_bounds__(THREADS, 1)
quad_kernel(float* __restrict__ out) {
    extern __shared__ float sm[];
    float*    sF = sm;
    unsigned* sP = (unsigned*)(sm + OFF_P);

    const int tid  = threadIdx.x;
    const int lane = tid & 31;
    const int warp = tid >> 5;
    const int b0 = blockIdx.x * BTILE;

    // ---- cooperative staging of sF (stride 65) and sP ----
    for (int idx = tid; idx < 2048; idx += THREADS) {
        int row = idx >> 4, c4 = (idx & 15) << 2;
        float4 v = *reinterpret_cast<const float4*>(
            g_fsum + (size_t)(b0 + row) * E_DIM + c4);
        sF[row * FSTR + c4 + 0] = v.x;
        sF[row * FSTR + c4 + 1] = v.y;
        sF[row * FSTR + c4 + 2] = v.z;
        sF[row * FSTR + c4 + 3] = v.w;
    }
    for (int k = tid; k < KPAD; k += THREADS) sP[k] = g_pair[k];
    __syncthreads();

    if (warp >= 8) {
        // ================= PRODUCER (128 threads) =================
        const int p = tid - 256;               // 0..127
        const int fb = p * FSTR;               // this thread's A row
        const uint32_t sB_base = smem_u32(sm + OFF_B0);

#pragma unroll 1
        for (int c = 0; c < NCHUNK; ++c) {
            const int s = c & 1;
            if (c >= 2) bar_sync(s ? EMPTY1 : EMPTY0);

            // cp.async B(c): 2048 float4, 16 per thread, coalesced
            {
                const unsigned* srcT = g_T;
                uint32_t dstb = sB_base + (uint32_t)(s ? STAGE * 4 : 0);
#pragma unroll
                for (int t = 0; t < 16; ++t) {
                    int idx = p + t * 128;           // float4 index
                    int row = idx >> 4, c4 = (idx & 15) << 2;
                    cp16(dstb + (uint32_t)(row * BSTR + c4) * 4u,
                         srcT + (size_t)row * KPAD + c * 64 + c4);
                }
                cp_commit();
            }
            // gen A(c): row p, 64 cols
            {
                float* dst = sm + (s ? OFF_A1 : OFF_A0) + p * ASTR;
                const int kb = c * 64;
#pragma unroll
                for (int q = 0; q < 16; ++q) {
                    unsigned p0 = sP[kb + 4*q + 0], p1 = sP[kb + 4*q + 1];
                    unsigned p2 = sP[kb + 4*q + 2], p3 = sP[kb + 4*q + 3];
                    float4 v;
                    v.x = __uint_as_float(f2tf(sF[fb + (p0 >> 8)] * sF[fb + (p0 & 255)]));
                    v.y = __uint_as_float(f2tf(sF[fb + (p1 >> 8)] * sF[fb + (p1 & 255)]));
                    v.z = __uint_as_float(f2tf(sF[fb + (p2 >> 8)] * sF[fb + (p2 & 255)]));
                    v.w = __uint_as_float(f2tf(sF[fb + (p3 >> 8)] * sF[fb + (p3 & 255)]));
                    *reinterpret_cast<float4*>(dst + 4*q) = v;
                }
            }
            cp_wait0();
            bar_arrive(s ? FULL1 : FULL0);
        }
    } else {
        // ================= CONSUMER (256 threads, 8 warps) =================
        const int l4 = lane >> 2, k4 = lane & 3;
        const int row_base = (warp & 3) * 32;     // 4-way m split
        const int col_base = (warp >> 2) * 64;    // 2-way n split

        float acc[2][8][4];
#pragma unroll
        for (int mt = 0; mt < 2; ++mt)
#pragma unroll
            for (int nt = 0; nt < 8; ++nt)
#pragma unroll
                for (int x = 0; x < 4; ++x) acc[mt][nt][x] = 0.f;

#pragma unroll 1
        for (int c = 0; c < NCHUNK; ++c) {
            const int s = c & 1;
            bar_sync(s ? FULL1 : FULL0);

            const float* A = sm + (s ? OFF_A1 : OFF_A0);
            const float* B = sm + (s ? OFF_B1 : OFF_B0);
#pragma unroll
            for (int kk = 0; kk < 8; ++kk) {
                const int kcol = kk * 8 + k4 * 2;
                float2 a0[2], a1[2];
#pragma unroll
                for (int mt = 0; mt < 2; ++mt) {
                    const float* ap = A + (row_base + mt * 16 + l4) * ASTR + kcol;
                    a0[mt] = *reinterpret_cast<const float2*>(ap);
                    a1[mt] = *reinterpret_cast<const float2*>(ap + 8 * ASTR);
                }
#pragma unroll
                for (int nt = 0; nt < 8; ++nt) {
                    float2 bb = *reinterpret_cast<const float2*>(
                        B + (col_base + nt * 8 + l4) * BSTR + kcol);
                    unsigned bf0 = __float_as_uint(bb.x);
                    unsigned bf1 = __float_as_uint(bb.y);
#pragma unroll
                    for (int mt = 0; mt < 2; ++mt)
                        mma8(acc[mt][nt],
                             __float_as_uint(a0[mt].x), __float_as_uint(a1[mt].x),
                             __float_as_uint(a0[mt].y), __float_as_uint(a1[mt].y),
                             bf0, bf1);
                }
            }
            bar_arrive(s ? EMPTY1 : EMPTY0);
        }

        // ---- epilogue: direct STG ----
#pragma unroll
        for (int mt = 0; mt < 2; ++mt) {
#pragma unroll
            for (int nt = 0; nt < 8; ++nt) {
                const int rr = b0 + row_base + mt * 16 + l4;
                const int cc = col_base + nt * 8 + k4 * 2;
                float2 v0 = make_float2(acc[mt][nt][0], acc[mt][nt][1]);
                float2 v1 = make_float2(acc[mt][nt][2], acc[mt][nt][3]);
                *reinterpret_cast<float2*>(out + (size_t)rr * U_DIM + cc) = v0;
                *reinterpret_cast<float2*>(out + (size_t)(rr + 8) * U_DIM + cc) = v1;
            }
        }
    }
}

extern "C" void kernel_launch(void* const* d_in, const int* in_sizes, int n_in,
                              void* d_out, int out_size) {
    const float* embeds = (const float*)d_in[0];   // (16384, 39, 64)
    const float* W      = (const float*)d_in[1];   // (128, 64, 64)
    float* out          = (float*)d_out;           // (16384, 128)

    static int smem_set = 0;
    if (!smem_set) {
        cudaFuncSetAttribute(quad_kernel,
                             cudaFuncAttributeMaxDynamicSharedMemorySize, SMEM_BYTES);
        smem_set = 1;
    }

    pairs_kernel<<<(KPAD + 255) / 256, 256>>>();
    fsum_kernel<<<(B_TOTAL * (E_DIM / 4)) / 256, 256>>>(embeds);
    tconv_kernel<<<(U_DIM * KPAD) / 256, 256>>>(W);
    quad_kernel<<<B_TOTAL / BTILE, THREADS, SMEM_BYTES>>>(out);
}

// round 10
// speedup vs baseline: 1.6668x; 1.1415x over previous
#include <cuda_runtime.h>
#include <cstdint>

#define B_TOTAL 16384
#define F_FIELDS 39
#define E_DIM 64
#define U_DIM 128
#define BTILE 128
#define THREADS 384          // 8 consumer warps + 4 producer warps
#define NGRP  288            // row-blocked groups of 8 (rows padded to mult of 8)
#define KPAD  2304           // NGRP*8
#define NCHUNK 36
#define FSTR 65
#define ASTR 72
#define BSTR 72
// smem float offsets
#define OFF_A0 8336          // sF = 128*65 + 16 pad
#define OFF_A1 17552
#define OFF_B0 26768
#define OFF_B1 35984
#define OFF_G  45200
#define SMEM_FLOATS 45488
#define SMEM_BYTES  (SMEM_FLOATS * 4)   // 181952 B, 1 CTA/SM

// named barrier ids (0 reserved for __syncthreads)
#define FULL0 1
#define FULL1 2
#define EMPTY0 3
#define EMPTY1 4

__device__ float    g_fsum[B_TOTAL * E_DIM];
__device__ unsigned g_T[U_DIM * KPAD];   // rna-tf32 bits of packed symmetric W (perm layout)
__device__ unsigned g_grp[NGRP];         // (i<<8)|j0 per group

__device__ __forceinline__ unsigned f2tf(float x) {
    unsigned y; asm("cvt.rna.tf32.f32 %0, %1;" : "=r"(y) : "f"(x)); return y;
}
__device__ __forceinline__ uint32_t smem_u32(const void* p) {
    uint32_t a;
    asm("{ .reg .u64 t; cvta.to.shared.u64 t, %1; cvt.u32.u64 %0, t; }" : "=r"(a) : "l"(p));
    return a;
}
__device__ __forceinline__ void cp16(uint32_t dst, const void* src) {
    asm volatile("cp.async.cg.shared.global [%0], [%1], 16;" :: "r"(dst), "l"(src) : "memory");
}
__device__ __forceinline__ void cp_commit() {
    asm volatile("cp.async.commit_group;" ::: "memory");
}
__device__ __forceinline__ void cp_wait0() {
    asm volatile("cp.async.wait_group 0;" ::: "memory");
}
__device__ __forceinline__ void bar_sync(int id) {
    asm volatile("bar.sync %0, %1;" :: "r"(id), "n"(THREADS) : "memory");
}
__device__ __forceinline__ void bar_arrive(int id) {
    asm volatile("bar.arrive %0, %1;" :: "r"(id), "n"(THREADS) : "memory");
}
__device__ __forceinline__ void mma8(float* c, unsigned a0, unsigned a1,
                                     unsigned a2, unsigned a3,
                                     unsigned b0, unsigned b1) {
    asm volatile(
        "mma.sync.aligned.m16n8k8.row.col.f32.tf32.tf32.f32 "
        "{%0,%1,%2,%3}, {%4,%5,%6,%7}, {%8,%9}, {%0,%1,%2,%3};"
        : "+f"(c[0]), "+f"(c[1]), "+f"(c[2]), "+f"(c[3])
        : "r"(a0), "r"(a1), "r"(a2), "r"(a3), "r"(b0), "r"(b1));
}

// ---------------- group table: row-blocked upper-tri, rows padded to 8 ----------------
// group g -> row i, j0 = i + 8*(g - cum_groups(i)). 288 groups total.
__global__ void grp_kernel() {
    int g = threadIdx.x;
    if (g >= NGRP) return;
    int cum = 0;
    for (int r = 0; r < 64; ++r) {
        int ng = (71 - r) >> 3;            // ceil((64-r)/8)
        if (g < cum + ng) {
            g_grp[g] = ((unsigned)r << 8) | (unsigned)(r + 8 * (g - cum));
            return;
        }
        cum += ng;
    }
}

// ---------------- fused prep: feat_sum + packed symmetric T (perm layout) ----------------
// blocks [0,1024): fsum.  blocks [1024,2176): tconv over 128*2304 entries.
__global__ void prep_kernel(const float* __restrict__ embeds,
                            const float* __restrict__ W) {
    if (blockIdx.x < 1024) {
        int idx = blockIdx.x * 256 + threadIdx.x;
        int b = idx >> 4;
        int e4 = idx & 15;
        const float4* p = reinterpret_cast<const float4*>(embeds)
                          + (size_t)b * (F_FIELDS * E_DIM / 4) + e4;
        float4 s = make_float4(0.f, 0.f, 0.f, 0.f);
#pragma unroll
        for (int f = 0; f < F_FIELDS; ++f) {
            float4 v = p[f * (E_DIM / 4)];
            s.x += v.x; s.y += v.y; s.z += v.z; s.w += v.w;
        }
        reinterpret_cast<float4*>(g_fsum)[idx] = s;
    } else {
        int idx = (blockIdx.x - 1024) * 256 + threadIdx.x;   // < 294912
        int u = idx / KPAD;
        int k = idx - u * KPAD;
        unsigned grp = g_grp[k >> 3];
        int n = k & 7;
        int o = (n >> 1) + ((n & 1) << 2);   // perm pos -> orig offset
        int i = grp >> 8;
        int j = (int)(grp & 255) + o;
        float v = 0.f;
        if (j < 64) {
            v = W[u * 4096 + i * 64 + j];
            if (i != j) v += W[u * 4096 + j * 64 + i];
        }
        g_T[idx] = f2tf(v);
    }
}

// ---------------- main GEMM: warp-specialized producer/consumer ----------------
// C[128b x 128u] += A[128 x 64k] * B[64k x 128], 36 chunks over padded K=2304.
// Warps 0-7: consumers (4m x 2n, 32x64 tiles) - frag LDS.64 + HMMA only.
// Warps 8-11: producers - row-blocked A-gen (uniform i per 8-group) + cp.async B.
__global__ void __launch_bounds__(THREADS, 1)
quad_kernel(float* __restrict__ out) {
    extern __shared__ float sm[];
    float*    sF = sm;
    unsigned* sG = (unsigned*)(sm + OFF_G);

    const int tid  = threadIdx.x;
    const int lane = tid & 31;
    const int warp = tid >> 5;
    const int b0 = blockIdx.x * BTILE;

    // ---- cooperative staging of sF (stride 65, +16 zero pad) and sG ----
    for (int idx = tid; idx < 2048; idx += THREADS) {
        int row = idx >> 4, c4 = (idx & 15) << 2;
        float4 v = *reinterpret_cast<const float4*>(
            g_fsum + (size_t)(b0 + row) * E_DIM + c4);
        sF[row * FSTR + c4 + 0] = v.x;
        sF[row * FSTR + c4 + 1] = v.y;
        sF[row * FSTR + c4 + 2] = v.z;
        sF[row * FSTR + c4 + 3] = v.w;
    }
    if (tid < 16) sF[128 * FSTR + tid] = 0.f;   // pad: last row may read j up to 70
    if (tid < NGRP) sG[tid] = g_grp[tid];
    __syncthreads();

    if (warp >= 8) {
        // ================= PRODUCER (128 threads) =================
        const int p = tid - 256;               // 0..127 (A row)
        const float* fr = sF + p * FSTR;
        const uint32_t sB_base = smem_u32(sm + OFF_B0);

#pragma unroll 1
        for (int c = 0; c < NCHUNK; ++c) {
            const int s = c & 1;
            if (c >= 2) bar_sync(s ? EMPTY1 : EMPTY0);

            // cp.async B(c): 2048 float4, 16 per thread, coalesced
            {
                uint32_t dstb = sB_base + (uint32_t)(s ? 9216 * 4 : 0);
#pragma unroll
                for (int t = 0; t < 16; ++t) {
                    int idx = p + t * 128;           // float4 index
                    int row = idx >> 4, c4 = (idx & 15) << 2;
                    cp16(dstb + (uint32_t)(row * BSTR + c4) * 4u,
                         g_T + (size_t)row * KPAD + c * 64 + c4);
                }
                cp_commit();
            }
            // gen A(c): row p, 8 groups of 8 cols; uniform i per group
            {
                float* dst = sm + (s ? OFF_A1 : OFF_A0) + p * ASTR;
#pragma unroll
                for (int g8 = 0; g8 < 8; ++g8) {
                    unsigned grp = sG[c * 8 + g8];
                    const float fi = fr[grp >> 8];
                    const float* fj = fr + (grp & 255);
                    float t0 = fi * fj[0], t1 = fi * fj[1];
                    float t2 = fi * fj[2], t3 = fi * fj[3];
                    float t4 = fi * fj[4], t5 = fi * fj[5];
                    float t6 = fi * fj[6], t7 = fi * fj[7];
                    // perm: pos 2t <- orig t, pos 2t+1 <- orig t+4
                    uint4 v0 = make_uint4(f2tf(t0), f2tf(t4), f2tf(t1), f2tf(t5));
                    uint4 v1 = make_uint4(f2tf(t2), f2tf(t6), f2tf(t3), f2tf(t7));
                    *reinterpret_cast<uint4*>(dst + g8 * 8)     = v0;
                    *reinterpret_cast<uint4*>(dst + g8 * 8 + 4) = v1;
                }
            }
            cp_wait0();
            bar_arrive(s ? FULL1 : FULL0);
        }
    } else {
        // ================= CONSUMER (256 threads, 8 warps) =================
        const int l4 = lane >> 2, k4 = lane & 3;
        const int row_base = (warp & 3) * 32;     // 4-way m split
        const int col_base = (warp >> 2) * 64;    // 2-way n split

        float acc[2][8][4];
#pragma unroll
        for (int mt = 0; mt < 2; ++mt)
#pragma unroll
            for (int nt = 0; nt < 8; ++nt)
#pragma unroll
                for (int x = 0; x < 4; ++x) acc[mt][nt][x] = 0.f;

#pragma unroll 1
        for (int c = 0; c < NCHUNK; ++c) {
            const int s = c & 1;
            bar_sync(s ? FULL1 : FULL0);

            const float* A = sm + (s ? OFF_A1 : OFF_A0);
            const float* B = sm + (s ? OFF_B1 : OFF_B0);
#pragma unroll
            for (int kk = 0; kk < 8; ++kk) {
                const int kcol = kk * 8 + k4 * 2;
                float2 a0[2], a1[2];
#pragma unroll
                for (int mt = 0; mt < 2; ++mt) {
                    const float* ap = A + (row_base + mt * 16 + l4) * ASTR + kcol;
                    a0[mt] = *reinterpret_cast<const float2*>(ap);
                    a1[mt] = *reinterpret_cast<const float2*>(ap + 8 * ASTR);
                }
#pragma unroll
                for (int nt = 0; nt < 8; ++nt) {
                    float2 bb = *reinterpret_cast<const float2*>(
                        B + (col_base + nt * 8 + l4) * BSTR + kcol);
                    unsigned bf0 = __float_as_uint(bb.x);
                    unsigned bf1 = __float_as_uint(bb.y);
#pragma unroll
                    for (int mt = 0; mt < 2; ++mt)
                        mma8(acc[mt][nt],
                             __float_as_uint(a0[mt].x), __float_as_uint(a1[mt].x),
                             __float_as_uint(a0[mt].y), __float_as_uint(a1[mt].y),
                             bf0, bf1);
                }
            }
            bar_arrive(s ? EMPTY1 : EMPTY0);
        }

        // ---- epilogue: direct STG ----
#pragma unroll
        for (int mt = 0; mt < 2; ++mt) {
#pragma unroll
            for (int nt = 0; nt < 8; ++nt) {
                const int rr = b0 + row_base + mt * 16 + l4;
                const int cc = col_base + nt * 8 + k4 * 2;
                float2 v0 = make_float2(acc[mt][nt][0], acc[mt][nt][1]);
                float2 v1 = make_float2(acc[mt][nt][2], acc[mt][nt][3]);
                *reinterpret_cast<float2*>(out + (size_t)rr * U_DIM + cc) = v0;
                *reinterpret_cast<float2*>(out + (size_t)(rr + 8) * U_DIM + cc) = v1;
            }
        }
    }
}

extern "C" void kernel_launch(void* const* d_in, const int* in_sizes, int n_in,
                              void* d_out, int out_size) {
    const float* embeds = (const float*)d_in[0];   // (16384, 39, 64)
    const float* W      = (const float*)d_in[1];   // (128, 64, 64)
    float* out          = (float*)d_out;           // (16384, 128)

    static int smem_set = 0;
    if (!smem_set) {
        cudaFuncSetAttribute(quad_kernel,
                             cudaFuncAttributeMaxDynamicSharedMemorySize, SMEM_BYTES);
        smem_set = 1;
    }

    grp_kernel<<<1, NGRP>>>();
    prep_kernel<<<1024 + (U_DIM * KPAD) / 256, 256>>>(embeds, W);
    quad_kernel<<<B_TOTAL / BTILE, THREADS, SMEM_BYTES>>>(out);
}